// round 4
// baseline (speedup 1.0000x reference)
#include <cuda_runtime.h>
#include <cstdint>

// ---------------------------------------------------------------------------
// QuadTreeDecoder round 4
//  - qt_wf:     WF[p][c] = head_w * F_c^T  (48x16 per level-5 node-child)
//  - qt_path4:  ONE kernel for levels 0..4. Block = (level-4 node, b-half);
//               each thread recomputes its root->node path (redundant, cheap),
//               then applies the level-4 transform; writes 1024-node acts.
//  - qt_l5_head: block = (level-5 node, b-half); y = (Wx+b) + WF_c * lat.
// ---------------------------------------------------------------------------

#define B_SZ 128

__device__ float g_actA[(size_t)B_SZ * 1024 * 64];          // level-4 output (33.5 MB)
__device__ float g_wf[(size_t)1024 * 4 * 48 * 16];          // 12.6 MB

// ---------------------------------------------------------------------------
__global__ __launch_bounds__(256)
void qt_wf_kernel(const float* __restrict__ ftl, const float* __restrict__ ftr,
                  const float* __restrict__ fbl, const float* __restrict__ fbr,
                  const float* __restrict__ head_w, float* __restrict__ wf)
{
    __shared__ float w_s[48][64];
    __shared__ float F_s[4][16][64];

    const int p    = blockIdx.x;
    const int tid  = threadIdx.x;
    const int node = 341 + p;

    for (int k = tid; k < 48 * 64; k += 256)
        w_s[k >> 6][k & 63] = head_w[k];
    {
        const float* s0 = ftl + (size_t)node * 1024;
        const float* s1 = ftr + (size_t)node * 1024;
        const float* s2 = fbl + (size_t)node * 1024;
        const float* s3 = fbr + (size_t)node * 1024;
        for (int k = tid; k < 1024; k += 256) {
            F_s[0][k >> 6][k & 63] = s0[k];
            F_s[1][k >> 6][k & 63] = s1[k];
            F_s[2][k >> 6][k & 63] = s2[k];
            F_s[3][k >> 6][k & 63] = s3[k];
        }
    }
    __syncthreads();

    if (tid < 192) {
        const int c = tid / 48;
        const int k = tid - c * 48;
        float acc[16];
#pragma unroll
        for (int r = 0; r < 16; r++) acc[r] = 0.f;
#pragma unroll 1
        for (int o = 0; o < 64; o += 4) {
            float4 wv = *(const float4*)&w_s[k][o];
#pragma unroll
            for (int r = 0; r < 16; r++) {
                float4 f = *(const float4*)&F_s[c][r][o];
                acc[r] += wv.x * f.x + wv.y * f.y + wv.z * f.z + wv.w * f.w;
            }
        }
        float* dst = wf + ((size_t)p * 4 + c) * (48 * 16) + (size_t)k * 16;
#pragma unroll
        for (int r = 0; r < 16; r += 4)
            *(float4*)(dst + r) = make_float4(acc[r], acc[r+1], acc[r+2], acc[r+3]);
    }
}

// ---------------------------------------------------------------------------
// Levels 0..4 in one kernel. blockIdx.x = p4*2 + q (p4 in [0,256), q = b-half).
// 64 threads = batch within half. Path ancestors recomputed per block.
// ---------------------------------------------------------------------------
__global__ __launch_bounds__(64)
void qt_path4(const float* __restrict__ x0, float* __restrict__ xout,
              const float* __restrict__ fin,
              const float* __restrict__ ftl, const float* __restrict__ ftr,
              const float* __restrict__ fbl, const float* __restrict__ fbr,
              const float* __restrict__ scale)
{
    __shared__ float fiP[4][16][64];   // path ancestors' fi (scale folded), levels 0..3
    __shared__ float FP [4][16][64];   // path ancestors' child-F
    __shared__ float fi4[16][64];      // level-4 fi (scale folded)
    __shared__ float F4 [4][16][64];   // level-4 all children

    const int bid = blockIdx.x;
    const int p4  = bid >> 1;          // level-4 input node, grid 16
    const int qh  = bid & 1;
    const int tid = threadIdx.x;

    // --- derive path: q[l] = input-node index at level l, ch[l] = child taken
    int q[5], ch[4];
    q[4] = p4;
    {
        int g = 16;
        for (int l = 4; l >= 1; l--) {
            int r = q[l] / g, c = q[l] - r * g;
            q[l - 1] = (r >> 1) * (g >> 1) + (c >> 1);
            ch[l - 1] = ((r & 1) << 1) | (c & 1);
            g >>= 1;
        }
    }
    const int offs[5] = {0, 1, 5, 21, 85};

    // --- stage factors
    for (int l = 0; l < 4; l++) {
        const int node = offs[l] + q[l];
        const float* fib = fin + (size_t)node * 1024;
        const float* scb = scale + (size_t)node * 16;
        const float* Fc  = (ch[l] == 0 ? ftl : ch[l] == 1 ? ftr : ch[l] == 2 ? fbl : fbr)
                           + (size_t)node * 1024;
        for (int k = tid; k < 1024; k += 64) {
            fiP[l][k >> 6][k & 63] = fib[k] * __ldg(&scb[k >> 6]);
            FP [l][k >> 6][k & 63] = Fc[k];
        }
    }
    {
        const int node = offs[4] + p4;
        const float* fib = fin + (size_t)node * 1024;
        const float* scb = scale + (size_t)node * 16;
        const float* s0 = ftl + (size_t)node * 1024;
        const float* s1 = ftr + (size_t)node * 1024;
        const float* s2 = fbl + (size_t)node * 1024;
        const float* s3 = fbr + (size_t)node * 1024;
        for (int k = tid; k < 1024; k += 64) {
            fi4[k >> 6][k & 63] = fib[k] * __ldg(&scb[k >> 6]);
            F4[0][k >> 6][k & 63] = s0[k];
            F4[1][k >> 6][k & 63] = s1[k];
            F4[2][k >> 6][k & 63] = s2[k];
            F4[3][k >> 6][k & 63] = s3[k];
        }
    }
    __syncthreads();

    const int b = qh * 64 + tid;

    // --- x in registers (statically indexed everywhere)
    float xr[64];
    {
        const float* xp = x0 + (size_t)b * 64;
#pragma unroll
        for (int i = 0; i < 64; i += 4) {
            float4 v = *(const float4*)(xp + i);
            xr[i] = v.x; xr[i+1] = v.y; xr[i+2] = v.z; xr[i+3] = v.w;
        }
    }

    float lat[16];

    // --- walk 4 ancestor levels
#pragma unroll 1
    for (int l = 0; l < 4; l++) {
        // lat[r] = dot(xr, fiP[l][r])   (r rolled, i unrolled: xr static)
#pragma unroll 1
        for (int r = 0; r < 16; r++) {
            float a = 0.f;
#pragma unroll
            for (int i = 0; i < 64; i += 4) {
                float4 f = *(const float4*)&fiP[l][r][i];
                a += xr[i] * f.x + xr[i+1] * f.y + xr[i+2] * f.z + xr[i+3] * f.w;
            }
            lat[r] = a;
        }
        // xr[o] += sum_r lat[r] * FP[l][r][o]   (o unrolled, r rolled)
#pragma unroll
        for (int o = 0; o < 64; o += 4) {
            float a0 = xr[o], a1 = xr[o+1], a2 = xr[o+2], a3 = xr[o+3];
#pragma unroll 1
            for (int r = 0; r < 16; r++) {
                float4 f = *(const float4*)&FP[l][r][o];
                float lv = lat[r];
                a0 += lv * f.x; a1 += lv * f.y; a2 += lv * f.z; a3 += lv * f.w;
            }
            xr[o] = a0; xr[o+1] = a1; xr[o+2] = a2; xr[o+3] = a3;
        }
    }

    // --- level 4: all four children
#pragma unroll 1
    for (int r = 0; r < 16; r++) {
        float a = 0.f;
#pragma unroll
        for (int i = 0; i < 64; i += 4) {
            float4 f = *(const float4*)&fi4[r][i];
            a += xr[i] * f.x + xr[i+1] * f.y + xr[i+2] * f.z + xr[i+3] * f.w;
        }
        lat[r] = a;
    }

    const int gr4 = p4 >> 4, gc4 = p4 & 15;
#pragma unroll 1
    for (int c = 0; c < 4; c++) {
        const int cn = (2 * gr4 + (c >> 1)) * 32 + 2 * gc4 + (c & 1);
        float* op = xout + ((size_t)b * 1024 + cn) * 64;
#pragma unroll
        for (int o = 0; o < 64; o += 4) {
            float a0 = xr[o], a1 = xr[o+1], a2 = xr[o+2], a3 = xr[o+3];
#pragma unroll 1
            for (int r = 0; r < 16; r++) {
                float4 f = *(const float4*)&F4[c][r][o];
                float lv = lat[r];
                a0 += lv * f.x; a1 += lv * f.y; a2 += lv * f.z; a3 += lv * f.w;
            }
            *(float4*)(op + o) = make_float4(a0, a1, a2, a3);
        }
    }
}

// ---------------------------------------------------------------------------
// Fused level5 + head. blockIdx.x = p5*2 + q; 64 threads = batch half.
// ---------------------------------------------------------------------------
__global__ __launch_bounds__(64)
void qt_l5_head(const float* __restrict__ xin,
                const float* __restrict__ fin, const float* __restrict__ scale,
                const float* __restrict__ wf,
                const float* __restrict__ head_w, const float* __restrict__ head_b,
                float* __restrict__ out)
{
    __shared__ float fi_s[16][64];
    __shared__ float w_s[48][64];
    __shared__ float wf_s[4][48][16];
    __shared__ float hb_s[48];

    const int bid  = blockIdx.x;
    const int p    = bid >> 1;          // level-5 parent, grid 32
    const int qh   = bid & 1;
    const int tid  = threadIdx.x;
    const int node = 341 + p;

    {
        const float* fib = fin + (size_t)node * 1024;
        const float* scb = scale + (size_t)node * 16;
        for (int k = tid; k < 1024; k += 64)
            fi_s[k >> 6][k & 63] = fib[k] * __ldg(&scb[k >> 6]);
        for (int k = tid; k < 48 * 64; k += 64)
            w_s[k >> 6][k & 63] = head_w[k];
        const float* wfp = wf + (size_t)p * (4 * 48 * 16);
        float* wfs = (float*)wf_s;
        for (int k = tid; k < 4 * 48 * 16; k += 64)
            wfs[k] = wfp[k];
        if (tid < 48) hb_s[tid] = head_b[tid];
    }
    __syncthreads();

    const int b = qh * 64 + tid;
    const float* xp = xin + ((size_t)b * 1024 + p) * 64;

    // lat
    float lat[16];
#pragma unroll
    for (int r = 0; r < 16; r++) lat[r] = 0.f;
#pragma unroll 1
    for (int i = 0; i < 64; i += 4) {
        float4 xv = *(const float4*)(xp + i);
#pragma unroll
        for (int r = 0; r < 16; r++) {
            float4 f = *(const float4*)&fi_s[r][i];
            lat[r] += xv.x * f.x + xv.y * f.y + xv.z * f.z + xv.w * f.w;
        }
    }

    // wx = W x + b
    float wx[48];
#pragma unroll
    for (int k = 0; k < 48; k++) wx[k] = hb_s[k];
#pragma unroll 1
    for (int i = 0; i < 64; i += 4) {
        float4 xv = *(const float4*)(xp + i);   // L1 hit
#pragma unroll
        for (int k = 0; k < 48; k++) {
            float4 wv = *(const float4*)&w_s[k][i];
            wx[k] += xv.x * wv.x + xv.y * wv.y + xv.z * wv.z + xv.w * wv.w;
        }
    }

    const int gr = p >> 5;
    const int gc = p & 31;

#pragma unroll 1
    for (int c = 0; c < 4; c++) {
        const int cn = (2 * gr + (c >> 1)) * 64 + 2 * gc + (c & 1);

        float acc[48];
#pragma unroll
        for (int k = 0; k < 48; k++) acc[k] = wx[k];

#pragma unroll
        for (int rs = 0; rs < 16; rs += 4) {
            const float l0 = lat[rs], l1 = lat[rs+1], l2 = lat[rs+2], l3 = lat[rs+3];
#pragma unroll
            for (int k = 0; k < 48; k++) {
                float4 f = *(const float4*)&wf_s[c][k][rs];
                acc[k] += l0 * f.x + l1 * f.y + l2 * f.z + l3 * f.w;
            }
        }

        const int sr = cn >> 6, sc = cn & 63;
#pragma unroll
        for (int oc = 0; oc < 3; oc++) {
#pragma unroll
            for (int pr = 0; pr < 4; pr++) {
                float4 v = make_float4(acc[pr * 12 + 0 + oc],
                                       acc[pr * 12 + 3 + oc],
                                       acc[pr * 12 + 6 + oc],
                                       acc[pr * 12 + 9 + oc]);
                size_t row = (size_t)(b * 3 + oc) * 256 + (sr * 4 + pr);
                *(float4*)(out + row * 256 + sc * 4) = v;
            }
        }
    }
}

// ---------------------------------------------------------------------------
extern "C" void kernel_launch(void* const* d_in, const int* in_sizes, int n_in,
                              void* d_out, int out_size)
{
    const float* x      = (const float*)d_in[0];
    const float* fin    = (const float*)d_in[1];
    const float* ftl    = (const float*)d_in[2];
    const float* ftr    = (const float*)d_in[3];
    const float* fbl    = (const float*)d_in[4];
    const float* fbr    = (const float*)d_in[5];
    const float* scale  = (const float*)d_in[6];
    const float* head_w = (const float*)d_in[7];
    const float* head_b = (const float*)d_in[8];
    float* out = (float*)d_out;

    float *bA, *wfb;
    cudaGetSymbolAddress((void**)&bA,  g_actA);
    cudaGetSymbolAddress((void**)&wfb, g_wf);

    qt_wf_kernel<<<1024, 256>>>(ftl, ftr, fbl, fbr, head_w, wfb);
    qt_path4<<<512, 64>>>(x, bA, fin, ftl, ftr, fbl, fbr, scale);
    qt_l5_head<<<2048, 64>>>(bA, fin, scale, wfb, head_w, head_b, out);
}

// round 5
// speedup vs baseline: 1.3674x; 1.3674x over previous
#include <cuda_runtime.h>
#include <cstdint>

// ---------------------------------------------------------------------------
// QuadTreeDecoder round 5
//   R3 structure (5 level kernels + WF precompute + fused l5+head), but
//   activations stored NODE-MAJOR float4-interleaved:
//        act[node][i4][b]  (float4; idx = (node*16 + i4)*128 + b)
//   so lane index == batch -> all activation LDG/STG are coalesced.
// ---------------------------------------------------------------------------

#define B_SZ 128

__device__ float4 g_actA[(size_t)1024 * 16 * B_SZ];   // 33.5 MB (l0,l2,l4 outs)
__device__ float4 g_actB[(size_t)256  * 16 * B_SZ];   //  8.4 MB (l1,l3 outs)
__device__ float  g_wf[(size_t)1024 * 4 * 48 * 16];   // 12.6 MB

// ---------------------------------------------------------------------------
// WF[p][c][k][r] = sum_o head_w[k][o] * F_c[node5][r][o]
// ---------------------------------------------------------------------------
__global__ __launch_bounds__(192)
void qt_wf_kernel(const float* __restrict__ ftl, const float* __restrict__ ftr,
                  const float* __restrict__ fbl, const float* __restrict__ fbr,
                  const float* __restrict__ head_w, float* __restrict__ wf)
{
    __shared__ float w_s[48][64];
    __shared__ float F_s[4][16][64];

    const int p    = blockIdx.x;
    const int tid  = threadIdx.x;
    const int node = 341 + p;

    for (int k = tid; k < 48 * 64; k += 192)
        w_s[k >> 6][k & 63] = head_w[k];
    {
        const float* s0 = ftl + (size_t)node * 1024;
        const float* s1 = ftr + (size_t)node * 1024;
        const float* s2 = fbl + (size_t)node * 1024;
        const float* s3 = fbr + (size_t)node * 1024;
        for (int k = tid; k < 1024; k += 192) {
            F_s[0][k >> 6][k & 63] = s0[k];
            F_s[1][k >> 6][k & 63] = s1[k];
            F_s[2][k >> 6][k & 63] = s2[k];
            F_s[3][k >> 6][k & 63] = s3[k];
        }
    }
    __syncthreads();

    const int c = tid / 48;           // 0..3
    const int k = tid - c * 48;       // 0..47

    float acc[16];
#pragma unroll
    for (int r = 0; r < 16; r++) acc[r] = 0.f;
#pragma unroll 1
    for (int o = 0; o < 64; o += 4) {
        float4 wv = *(const float4*)&w_s[k][o];
#pragma unroll
        for (int r = 0; r < 16; r++) {
            float4 f = *(const float4*)&F_s[c][r][o];
            acc[r] += wv.x * f.x + wv.y * f.y + wv.z * f.z + wv.w * f.w;
        }
    }
    float* dst = wf + ((size_t)p * 4 + c) * (48 * 16) + (size_t)k * 16;
#pragma unroll
    for (int r = 0; r < 16; r += 4)
        *(float4*)(dst + r) = make_float4(acc[r], acc[r+1], acc[r+2], acc[r+3]);
}

// ---------------------------------------------------------------------------
// One level. blockIdx.x = ((p*4 + c)*2 + qh); 64 threads = batch within half.
// xin: node-major interleaved (float4)[n*16*128], unless in_bmajor (level 0:
//      the original x, [b][64]). xout: node-major interleaved [4n*16*128].
// ---------------------------------------------------------------------------
__global__ __launch_bounds__(64)
void qt_level(const float4* __restrict__ xin, const float* __restrict__ x0,
              float4* __restrict__ xout,
              const float* __restrict__ fin,
              const float* __restrict__ ftl, const float* __restrict__ ftr,
              const float* __restrict__ fbl, const float* __restrict__ fbr,
              const float* __restrict__ scale,
              int n, int off, int gside, int in_bmajor)
{
    __shared__ float fi_s[16][64];   // scale folded
    __shared__ float F_s[16][64];    // this block's child

    const int bid  = blockIdx.x;
    const int p    = bid >> 3;
    const int c    = (bid >> 1) & 3;
    const int qh   = bid & 1;
    const int tid  = threadIdx.x;
    const int node = off + p;

    const float* Fc = (c == 0 ? ftl : c == 1 ? ftr : c == 2 ? fbl : fbr)
                      + (size_t)node * 1024;
    const float* fib = fin + (size_t)node * 1024;
    const float* scb = scale + (size_t)node * 16;

    for (int k = tid; k < 1024; k += 64) {
        fi_s[k >> 6][k & 63] = fib[k] * __ldg(&scb[k >> 6]);
        F_s [k >> 6][k & 63] = Fc[k];
    }
    __syncthreads();

    const int b = qh * 64 + tid;

    // ---- x into registers (coalesced for interleaved layout)
    float xr[64];
    if (in_bmajor) {
        const float* xp = x0 + (size_t)b * 64;
#pragma unroll
        for (int i4 = 0; i4 < 16; i4++) {
            float4 v = *(const float4*)(xp + i4 * 4);
            xr[i4*4] = v.x; xr[i4*4+1] = v.y; xr[i4*4+2] = v.z; xr[i4*4+3] = v.w;
        }
    } else {
        const float4* xp = xin + ((size_t)p * 16) * 128 + b;
#pragma unroll
        for (int i4 = 0; i4 < 16; i4++) {
            float4 v = xp[i4 * 128];
            xr[i4*4] = v.x; xr[i4*4+1] = v.y; xr[i4*4+2] = v.z; xr[i4*4+3] = v.w;
        }
    }

    // ---- lat[r] = dot(xr, fi_s[r]) (16 independent acc chains)
    float lat[16];
#pragma unroll
    for (int r = 0; r < 16; r++) lat[r] = 0.f;
#pragma unroll 1
    for (int i = 0; i < 64; i += 4) {
        const float x0v = xr[i], x1v = xr[i+1], x2v = xr[i+2], x3v = xr[i+3];
#pragma unroll
        for (int r = 0; r < 16; r++) {
            float4 f = *(const float4*)&fi_s[r][i];
            lat[r] += x0v * f.x + x1v * f.y + x2v * f.z + x3v * f.w;
        }
    }

    // ---- child output (coalesced interleaved writes)
    const int gr = p / gside;
    const int gc = p - gr * gside;
    const int cn = (2 * gr + (c >> 1)) * (2 * gside) + 2 * gc + (c & 1);
    float4* op = xout + ((size_t)cn * 16) * 128 + b;

#pragma unroll
    for (int o4 = 0; o4 < 16; o4++) {
        const int o = o4 * 4;
        float a0 = xr[o], a1 = xr[o+1], a2 = xr[o+2], a3 = xr[o+3];
#pragma unroll 1
        for (int r = 0; r < 16; r++) {
            float4 f = *(const float4*)&F_s[r][o];
            const float lv = lat[r];
            a0 += lv * f.x; a1 += lv * f.y; a2 += lv * f.z; a3 += lv * f.w;
        }
        op[o4 * 128] = make_float4(a0, a1, a2, a3);
    }
}

// ---------------------------------------------------------------------------
// Fused level5 + head. Block = level-5 parent p (1024 blocks), 128 thr = batch.
// xin: interleaved [1024*16*128] float4 (coalesced reads).
// ---------------------------------------------------------------------------
__global__ __launch_bounds__(128)
void qt_l5_head(const float4* __restrict__ xin,
                const float* __restrict__ fin, const float* __restrict__ scale,
                const float* __restrict__ wf,
                const float* __restrict__ head_w, const float* __restrict__ head_b,
                float* __restrict__ out)
{
    __shared__ float fi_s[16][64];
    __shared__ float w_s[48][64];
    __shared__ float wf_s[4][48][16];
    __shared__ float hb_s[48];

    const int p    = blockIdx.x;     // 0..1023
    const int tid  = threadIdx.x;    // batch
    const int node = 341 + p;

    {
        const float* fib = fin + (size_t)node * 1024;
        const float* scb = scale + (size_t)node * 16;
        for (int k = tid; k < 1024; k += 128)
            fi_s[k >> 6][k & 63] = fib[k] * __ldg(&scb[k >> 6]);
        for (int k = tid; k < 48 * 64; k += 128)
            w_s[k >> 6][k & 63] = head_w[k];
        const float4* wfp = (const float4*)(wf + (size_t)p * (4 * 48 * 16));
        float4* wfs = (float4*)wf_s;
        for (int k = tid; k < 4 * 48 * 4; k += 128)   // 768 float4
            wfs[k] = wfp[k];
        if (tid < 48) hb_s[tid] = head_b[tid];
    }
    __syncthreads();

    const int b = tid;

    // x into registers (coalesced)
    float xr[64];
    {
        const float4* xp = xin + ((size_t)p * 16) * 128 + b;
#pragma unroll
        for (int i4 = 0; i4 < 16; i4++) {
            float4 v = xp[i4 * 128];
            xr[i4*4] = v.x; xr[i4*4+1] = v.y; xr[i4*4+2] = v.z; xr[i4*4+3] = v.w;
        }
    }

    // lat
    float lat[16];
#pragma unroll
    for (int r = 0; r < 16; r++) lat[r] = 0.f;
#pragma unroll 1
    for (int i = 0; i < 64; i += 4) {
        const float x0v = xr[i], x1v = xr[i+1], x2v = xr[i+2], x3v = xr[i+3];
#pragma unroll
        for (int r = 0; r < 16; r++) {
            float4 f = *(const float4*)&fi_s[r][i];
            lat[r] += x0v * f.x + x1v * f.y + x2v * f.z + x3v * f.w;
        }
    }

    // wx = W x + b
    float wx[48];
#pragma unroll
    for (int k = 0; k < 48; k++) wx[k] = hb_s[k];
#pragma unroll 1
    for (int i = 0; i < 64; i += 4) {
        const float x0v = xr[i], x1v = xr[i+1], x2v = xr[i+2], x3v = xr[i+3];
#pragma unroll
        for (int k = 0; k < 48; k++) {
            float4 wv = *(const float4*)&w_s[k][i];
            wx[k] += x0v * wv.x + x1v * wv.y + x2v * wv.z + x3v * wv.w;
        }
    }

    const int gr = p >> 5;
    const int gc = p & 31;

#pragma unroll 1
    for (int c = 0; c < 4; c++) {
        const int cn = (2 * gr + (c >> 1)) * 64 + 2 * gc + (c & 1);

        float acc[48];
#pragma unroll
        for (int k = 0; k < 48; k++) acc[k] = wx[k];

#pragma unroll
        for (int rs = 0; rs < 16; rs += 4) {
            const float l0 = lat[rs], l1 = lat[rs+1], l2 = lat[rs+2], l3 = lat[rs+3];
#pragma unroll
            for (int k = 0; k < 48; k++) {
                float4 f = *(const float4*)&wf_s[c][k][rs];
                acc[k] += l0 * f.x + l1 * f.y + l2 * f.z + l3 * f.w;
            }
        }

        // y[b, cn, k] -> pixels, k = pr*12 + pc*3 + oc
        const int sr = cn >> 6, sc = cn & 63;
#pragma unroll
        for (int oc = 0; oc < 3; oc++) {
#pragma unroll
            for (int pr = 0; pr < 4; pr++) {
                float4 v = make_float4(acc[pr * 12 + 0 + oc],
                                       acc[pr * 12 + 3 + oc],
                                       acc[pr * 12 + 6 + oc],
                                       acc[pr * 12 + 9 + oc]);
                size_t row = (size_t)(b * 3 + oc) * 256 + (sr * 4 + pr);
                *(float4*)(out + row * 256 + sc * 4) = v;
            }
        }
    }
}

// ---------------------------------------------------------------------------
extern "C" void kernel_launch(void* const* d_in, const int* in_sizes, int n_in,
                              void* d_out, int out_size)
{
    const float* x      = (const float*)d_in[0];
    const float* fin    = (const float*)d_in[1];
    const float* ftl    = (const float*)d_in[2];
    const float* ftr    = (const float*)d_in[3];
    const float* fbl    = (const float*)d_in[4];
    const float* fbr    = (const float*)d_in[5];
    const float* scale  = (const float*)d_in[6];
    const float* head_w = (const float*)d_in[7];
    const float* head_b = (const float*)d_in[8];
    float* out = (float*)d_out;

    float4 *bA, *bB;
    float  *wfb;
    cudaGetSymbolAddress((void**)&bA,  g_actA);
    cudaGetSymbolAddress((void**)&bB,  g_actB);
    cudaGetSymbolAddress((void**)&wfb, g_wf);

    qt_wf_kernel<<<1024, 192>>>(ftl, ftr, fbl, fbr, head_w, wfb);

    const int ns[5]   = {1, 4, 16, 64, 256};
    const int offs[5] = {0, 1, 5, 21, 85};
    const int gs[5]   = {1, 2, 4, 8, 16};

    const float4* cur = nullptr;
    for (int l = 0; l < 5; l++) {
        float4* o = (l & 1) ? bB : bA;
        qt_level<<<ns[l] * 8, 64>>>(cur, x, o, fin, ftl, ftr, fbl, fbr, scale,
                                    ns[l], offs[l], gs[l], (l == 0) ? 1 : 0);
        cur = o;
    }

    qt_l5_head<<<1024, 128>>>(cur, fin, scale, wfb, head_w, head_b, out);
}

// round 6
// speedup vs baseline: 2.0003x; 1.4629x over previous
#include <cuda_runtime.h>
#include <cstdint>

// ---------------------------------------------------------------------------
// QuadTreeDecoder round 6
//  All per-thread x state lives in SMEM columns (x_s[i4][tid]) -> no dynamic
//  register indexing / local-memory spills; x staged with MLP=16 coalesced.
//  Kernels: qt_wf, qt_l01 (levels 0+1), qt_l23 (levels 2+3), qt_l4, qt_l5_head.
//  Activations node-major float4-interleaved: act[node][i4][b].
// ---------------------------------------------------------------------------

__device__ float4 g_x2[(size_t)16   * 16 * 128];   // 128 KB
__device__ float4 g_x4[(size_t)256  * 16 * 128];   // 2 MB
__device__ float4 g_x5[(size_t)1024 * 16 * 128];   // 33.5 MB
__device__ float  g_wf[(size_t)1024 * 4 * 48 * 16];

// ---------------------------------------------------------------------------
// helpers (macros keep everything statically unrolled where it matters)
// ---------------------------------------------------------------------------
__device__ __forceinline__ void stage_factor(float dst[16][64], const float* __restrict__ src,
                                             const float* __restrict__ sc, int tid, int nthr)
{
    const float4* s4 = (const float4*)src;
    float4* d4 = (float4*)dst;
    if (sc) {
        for (int idx = tid; idx < 256; idx += nthr) {
            float4 v = s4[idx];
            float s = __ldg(&sc[idx >> 4]);
            v.x *= s; v.y *= s; v.z *= s; v.w *= s;
            d4[idx] = v;
        }
    } else {
        for (int idx = tid; idx < 256; idx += nthr)
            d4[idx] = s4[idx];
    }
}

// lat[r] = dot(x_col, fi[r]); x from x_s column tid
#define LAT_FROM_SMEM(lat, fi_s, x_s, tid)                                   \
    {                                                                        \
        _Pragma("unroll")                                                    \
        for (int r = 0; r < 16; r++) lat[r] = 0.f;                           \
        _Pragma("unroll 4")                                                  \
        for (int i4 = 0; i4 < 16; i4++) {                                    \
            float4 xv = x_s[i4][tid];                                        \
            _Pragma("unroll")                                                \
            for (int r = 0; r < 16; r++) {                                   \
                float4 f = *(const float4*)&fi_s[r][i4 * 4];                 \
                lat[r] += xv.x * f.x + xv.y * f.y + xv.z * f.z + xv.w * f.w; \
            }                                                                \
        }                                                                    \
    }

// x_col += F^T lat, result kept in smem column (safe: per-thread column)
#define UPDATE_SMEM(x_s, F_s, lat, tid)                                      \
    {                                                                        \
        _Pragma("unroll 4")                                                  \
        for (int o4 = 0; o4 < 16; o4++) {                                    \
            float4 a = x_s[o4][tid];                                         \
            _Pragma("unroll")                                                \
            for (int r = 0; r < 16; r++) {                                   \
                float4 f = *(const float4*)&F_s[r][o4 * 4];                  \
                const float lv = lat[r];                                     \
                a.x += lv * f.x; a.y += lv * f.y;                            \
                a.z += lv * f.z; a.w += lv * f.w;                            \
            }                                                                \
            x_s[o4][tid] = a;                                                \
        }                                                                    \
    }

// out[cn] = x_col + F^T lat, streamed to global (coalesced interleaved)
#define EMIT_GLOBAL(outp, x_s, F_s, lat, tid)                                \
    {                                                                        \
        _Pragma("unroll 4")                                                  \
        for (int o4 = 0; o4 < 16; o4++) {                                    \
            float4 a = x_s[o4][tid];                                         \
            _Pragma("unroll")                                                \
            for (int r = 0; r < 16; r++) {                                   \
                float4 f = *(const float4*)&F_s[r][o4 * 4];                  \
                const float lv = lat[r];                                     \
                a.x += lv * f.x; a.y += lv * f.y;                            \
                a.z += lv * f.z; a.w += lv * f.w;                            \
            }                                                                \
            (outp)[o4 * 128] = a;                                            \
        }                                                                    \
    }

// ---------------------------------------------------------------------------
// WF[p][c][k][r] = sum_o head_w[k][o] * F_c[341+p][r][o].  4096 blocks.
// ---------------------------------------------------------------------------
__global__ __launch_bounds__(64)
void qt_wf_kernel(const float* __restrict__ ftl, const float* __restrict__ ftr,
                  const float* __restrict__ fbl, const float* __restrict__ fbr,
                  const float* __restrict__ head_w, float* __restrict__ wf)
{
    __shared__ float F_s[16][64];

    const int bid = blockIdx.x;
    const int p   = bid >> 2;
    const int c   = bid & 3;
    const int tid = threadIdx.x;
    const int node = 341 + p;

    const float* Fc = (c == 0 ? ftl : c == 1 ? ftr : c == 2 ? fbl : fbr)
                      + (size_t)node * 1024;
    stage_factor(F_s, Fc, nullptr, tid, 64);
    __syncthreads();

    if (tid < 48) {
        const int k = tid;
        const float4* wrow = (const float4*)(head_w + (size_t)k * 64);
        float acc[16];
#pragma unroll
        for (int r = 0; r < 16; r++) acc[r] = 0.f;
#pragma unroll 4
        for (int o4 = 0; o4 < 16; o4++) {
            float4 wv = __ldg(&wrow[o4]);
#pragma unroll
            for (int r = 0; r < 16; r++) {
                float4 f = *(const float4*)&F_s[r][o4 * 4];
                acc[r] += wv.x * f.x + wv.y * f.y + wv.z * f.z + wv.w * f.w;
            }
        }
        float* dst = wf + ((size_t)p * 4 + c) * (48 * 16) + (size_t)k * 16;
#pragma unroll
        for (int r = 0; r < 16; r += 4)
            *(float4*)(dst + r) = make_float4(acc[r], acc[r+1], acc[r+2], acc[r+3]);
    }
}

// ---------------------------------------------------------------------------
// Levels 0+1 fused. bid = (p1*4 + c1)*2 + qh. 32 blocks, 64 threads = batch.
// ---------------------------------------------------------------------------
__global__ __launch_bounds__(64)
void qt_l01(const float* __restrict__ x0, float4* __restrict__ xout,
            const float* __restrict__ fin,
            const float* __restrict__ ftl, const float* __restrict__ ftr,
            const float* __restrict__ fbl, const float* __restrict__ fbr,
            const float* __restrict__ scale)
{
    __shared__ float fiA[16][64], FA[16][64], fiB[16][64], FB[16][64];
    __shared__ float4 x_s[16][64];

    const int bid = blockIdx.x;
    const int p1  = bid >> 3;          // level-1 input node = child of root
    const int c1  = (bid >> 1) & 3;
    const int qh  = bid & 1;
    const int tid = threadIdx.x;

    const float* FcA = (p1 == 0 ? ftl : p1 == 1 ? ftr : p1 == 2 ? fbl : fbr);
    const int nodeB = 1 + p1;
    const float* FcB = (c1 == 0 ? ftl : c1 == 1 ? ftr : c1 == 2 ? fbl : fbr)
                       + (size_t)nodeB * 1024;

    stage_factor(fiA, fin, scale, tid, 64);
    stage_factor(FA,  FcA, nullptr, tid, 64);
    stage_factor(fiB, fin + (size_t)nodeB * 1024, scale + (size_t)nodeB * 16, tid, 64);
    stage_factor(FB,  FcB, nullptr, tid, 64);

    // x0 is b-major (B,1,64); tiny, scattered OK
    {
        const int b = qh * 64 + tid;
        const float4* xp = (const float4*)(x0 + (size_t)b * 64);
#pragma unroll
        for (int i4 = 0; i4 < 16; i4++)
            x_s[i4][tid] = xp[i4];
    }
    __syncthreads();

    float lat[16];
    LAT_FROM_SMEM(lat, fiA, x_s, tid)
    UPDATE_SMEM(x_s, FA, lat, tid)          // x_s now holds x1[p1]
    LAT_FROM_SMEM(lat, fiB, x_s, tid)

    const int gr = p1 >> 1, gc = p1 & 1;
    const int cn = (2 * gr + (c1 >> 1)) * 4 + 2 * gc + (c1 & 1);
    float4* op = xout + ((size_t)cn * 16) * 128 + qh * 64 + tid;
    EMIT_GLOBAL(op, x_s, FB, lat, tid)
}

// ---------------------------------------------------------------------------
// Levels 2+3 fused. bid = (p3*4 + c3)*2 + qh. 512 blocks.
// p3 = level-3 input node (grid 8); derive its level-2 parent p2 and c2.
// ---------------------------------------------------------------------------
__global__ __launch_bounds__(64)
void qt_l23(const float4* __restrict__ xin, float4* __restrict__ xout,
            const float* __restrict__ fin,
            const float* __restrict__ ftl, const float* __restrict__ ftr,
            const float* __restrict__ fbl, const float* __restrict__ fbr,
            const float* __restrict__ scale)
{
    __shared__ float fiA[16][64], FA[16][64], fiB[16][64], FB[16][64];
    __shared__ float4 x_s[16][64];

    const int bid = blockIdx.x;
    const int p3  = bid >> 3;
    const int c3  = (bid >> 1) & 3;
    const int qh  = bid & 1;
    const int tid = threadIdx.x;

    const int r3 = p3 >> 3, k3 = p3 & 7;
    const int p2 = (r3 >> 1) * 4 + (k3 >> 1);
    const int c2 = ((r3 & 1) << 1) | (k3 & 1);

    const int nodeA = 5 + p2;
    const int nodeB = 21 + p3;
    const float* FcA = (c2 == 0 ? ftl : c2 == 1 ? ftr : c2 == 2 ? fbl : fbr)
                       + (size_t)nodeA * 1024;
    const float* FcB = (c3 == 0 ? ftl : c3 == 1 ? ftr : c3 == 2 ? fbl : fbr)
                       + (size_t)nodeB * 1024;

    stage_factor(fiA, fin + (size_t)nodeA * 1024, scale + (size_t)nodeA * 16, tid, 64);
    stage_factor(FA,  FcA, nullptr, tid, 64);
    stage_factor(fiB, fin + (size_t)nodeB * 1024, scale + (size_t)nodeB * 16, tid, 64);
    stage_factor(FB,  FcB, nullptr, tid, 64);

    {
        const float4* xp = xin + ((size_t)p2 * 16) * 128 + qh * 64 + tid;
#pragma unroll
        for (int i4 = 0; i4 < 16; i4++)
            x_s[i4][tid] = xp[i4 * 128];
    }
    __syncthreads();

    float lat[16];
    LAT_FROM_SMEM(lat, fiA, x_s, tid)
    UPDATE_SMEM(x_s, FA, lat, tid)          // x_s now holds x3[p3]
    LAT_FROM_SMEM(lat, fiB, x_s, tid)

    const int gr = p3 >> 3, gc = p3 & 7;
    const int cn = (2 * gr + (c3 >> 1)) * 16 + 2 * gc + (c3 & 1);
    float4* op = xout + ((size_t)cn * 16) * 128 + qh * 64 + tid;
    EMIT_GLOBAL(op, x_s, FB, lat, tid)
}

// ---------------------------------------------------------------------------
// Level 4. bid = (p4*4 + c)*2 + qh. 2048 blocks.
// ---------------------------------------------------------------------------
__global__ __launch_bounds__(64)
void qt_l4(const float4* __restrict__ xin, float4* __restrict__ xout,
           const float* __restrict__ fin,
           const float* __restrict__ ftl, const float* __restrict__ ftr,
           const float* __restrict__ fbl, const float* __restrict__ fbr,
           const float* __restrict__ scale)
{
    __shared__ float fiA[16][64], FA[16][64];
    __shared__ float4 x_s[16][64];

    const int bid = blockIdx.x;
    const int p4  = bid >> 3;
    const int c   = (bid >> 1) & 3;
    const int qh  = bid & 1;
    const int tid = threadIdx.x;
    const int node = 85 + p4;

    const float* Fc = (c == 0 ? ftl : c == 1 ? ftr : c == 2 ? fbl : fbr)
                      + (size_t)node * 1024;
    stage_factor(fiA, fin + (size_t)node * 1024, scale + (size_t)node * 16, tid, 64);
    stage_factor(FA,  Fc, nullptr, tid, 64);
    {
        const float4* xp = xin + ((size_t)p4 * 16) * 128 + qh * 64 + tid;
#pragma unroll
        for (int i4 = 0; i4 < 16; i4++)
            x_s[i4][tid] = xp[i4 * 128];
    }
    __syncthreads();

    float lat[16];
    LAT_FROM_SMEM(lat, fiA, x_s, tid)

    const int gr = p4 >> 4, gc = p4 & 15;
    const int cn = (2 * gr + (c >> 1)) * 32 + 2 * gc + (c & 1);
    float4* op = xout + ((size_t)cn * 16) * 128 + qh * 64 + tid;
    EMIT_GLOBAL(op, x_s, FA, lat, tid)
}

// ---------------------------------------------------------------------------
// Fused level 5 + head. bid = p*2 + qh (2048 blocks), 64 threads = batch half.
//   single pass over x: lat (16) and wx = Wx+b (48) together; then per child
//   y = wx + WF_c * lat -> pixels.
// ---------------------------------------------------------------------------
__global__ __launch_bounds__(64)
void qt_l5_head(const float4* __restrict__ xin,
                const float* __restrict__ fin, const float* __restrict__ scale,
                const float* __restrict__ wf,
                const float* __restrict__ head_w, const float* __restrict__ head_b,
                float* __restrict__ out)
{
    __shared__ float fi_s[16][64];
    __shared__ float w_s[48][64];
    __shared__ float wf_s[4][48][16];
    __shared__ float hb_s[48];
    __shared__ float4 x_s[16][64];

    const int bid  = blockIdx.x;
    const int p    = bid >> 1;
    const int qh   = bid & 1;
    const int tid  = threadIdx.x;
    const int node = 341 + p;

    stage_factor(fi_s, fin + (size_t)node * 1024, scale + (size_t)node * 16, tid, 64);
    {
        const float4* w4 = (const float4*)head_w;
        float4* d4 = (float4*)w_s;
        for (int k = tid; k < 768; k += 64) d4[k] = w4[k];
        const float4* wfp = (const float4*)(wf + (size_t)p * (4 * 48 * 16));
        float4* wfs = (float4*)wf_s;
        for (int k = tid; k < 768; k += 64) wfs[k] = wfp[k];
        if (tid < 48) hb_s[tid] = head_b[tid];
        const float4* xp = xin + ((size_t)p * 16) * 128 + qh * 64 + tid;
#pragma unroll
        for (int i4 = 0; i4 < 16; i4++)
            x_s[i4][tid] = xp[i4 * 128];
    }
    __syncthreads();

    const int b = qh * 64 + tid;

    float lat[16];
    float wx[48];
#pragma unroll
    for (int r = 0; r < 16; r++) lat[r] = 0.f;
#pragma unroll
    for (int k = 0; k < 48; k++) wx[k] = hb_s[k];

#pragma unroll 2
    for (int i4 = 0; i4 < 16; i4++) {
        float4 xv = x_s[i4][tid];
#pragma unroll
        for (int r = 0; r < 16; r++) {
            float4 f = *(const float4*)&fi_s[r][i4 * 4];
            lat[r] += xv.x * f.x + xv.y * f.y + xv.z * f.z + xv.w * f.w;
        }
#pragma unroll
        for (int k = 0; k < 48; k++) {
            float4 wv = *(const float4*)&w_s[k][i4 * 4];
            wx[k] += xv.x * wv.x + xv.y * wv.y + xv.z * wv.z + xv.w * wv.w;
        }
    }

    const int gr = p >> 5, gc = p & 31;

#pragma unroll 1
    for (int c = 0; c < 4; c++) {
        const int cn = (2 * gr + (c >> 1)) * 64 + 2 * gc + (c & 1);

        float acc[48];
#pragma unroll
        for (int k = 0; k < 48; k++) acc[k] = wx[k];

#pragma unroll
        for (int rs = 0; rs < 16; rs += 4) {
            const float l0 = lat[rs], l1 = lat[rs+1], l2 = lat[rs+2], l3 = lat[rs+3];
#pragma unroll
            for (int k = 0; k < 48; k++) {
                float4 f = *(const float4*)&wf_s[c][k][rs];
                acc[k] += l0 * f.x + l1 * f.y + l2 * f.z + l3 * f.w;
            }
        }

        const int sr = cn >> 6, sc = cn & 63;
#pragma unroll
        for (int oc = 0; oc < 3; oc++) {
#pragma unroll
            for (int pr = 0; pr < 4; pr++) {
                float4 v = make_float4(acc[pr * 12 + 0 + oc],
                                       acc[pr * 12 + 3 + oc],
                                       acc[pr * 12 + 6 + oc],
                                       acc[pr * 12 + 9 + oc]);
                size_t row = (size_t)(b * 3 + oc) * 256 + (sr * 4 + pr);
                *(float4*)(out + row * 256 + sc * 4) = v;
            }
        }
    }
}

// ---------------------------------------------------------------------------
extern "C" void kernel_launch(void* const* d_in, const int* in_sizes, int n_in,
                              void* d_out, int out_size)
{
    const float* x      = (const float*)d_in[0];
    const float* fin    = (const float*)d_in[1];
    const float* ftl    = (const float*)d_in[2];
    const float* ftr    = (const float*)d_in[3];
    const float* fbl    = (const float*)d_in[4];
    const float* fbr    = (const float*)d_in[5];
    const float* scale  = (const float*)d_in[6];
    const float* head_w = (const float*)d_in[7];
    const float* head_b = (const float*)d_in[8];
    float* out = (float*)d_out;

    float4 *x2, *x4, *x5;
    float  *wfb;
    cudaGetSymbolAddress((void**)&x2,  g_x2);
    cudaGetSymbolAddress((void**)&x4,  g_x4);
    cudaGetSymbolAddress((void**)&x5,  g_x5);
    cudaGetSymbolAddress((void**)&wfb, g_wf);

    qt_wf_kernel<<<4096, 64>>>(ftl, ftr, fbl, fbr, head_w, wfb);
    qt_l01<<<32,   64>>>(x,  x2, fin, ftl, ftr, fbl, fbr, scale);
    qt_l23<<<512,  64>>>(x2, x4, fin, ftl, ftr, fbl, fbr, scale);
    qt_l4 <<<2048, 64>>>(x4, x5, fin, ftl, ftr, fbl, fbr, scale);
    qt_l5_head<<<2048, 64>>>(x5, fin, scale, wfb, head_w, head_b, out);
}